// round 9
// baseline (speedup 1.0000x reference)
#include <cuda_runtime.h>
#include <cuda_bf16.h>
#include <stdint.h>

// ---------------- problem constants ----------------
#define H_DIM 2048
#define I_DIM 4096
#define E_NUM 8
#define T_NUM 4096   // B*S
#define TOPK  2

#define TM 128
#define TN 64        // CTA N-tile (warp tile stays 32x32; 8 warps = 4x2)
#define TK 32
#define NTHREADS 256
#define RS 80        // SMEM row stride bytes (32 bf16 = 64B + 16B pad)

// ---------------- scratch (__device__ globals: allocation-free) ----------------
__device__ int   g_tok[T_NUM * TOPK];
__device__ float g_wgt[T_NUM * TOPK];
__device__ int   g_cnt[E_NUM];
__device__ int   g_off[E_NUM + 1];

#define NW ((size_t)E_NUM * I_DIM * H_DIM)
__device__ __nv_bfloat16 g_xh[(size_t)T_NUM * H_DIM];
__device__ __nv_bfloat16 g_xl[(size_t)T_NUM * H_DIM];
__device__ __nv_bfloat16 g_gh[NW];
__device__ __nv_bfloat16 g_gl[NW];
__device__ __nv_bfloat16 g_uh[NW];
__device__ __nv_bfloat16 g_ul[NW];
__device__ __nv_bfloat16 g_dh[NW];
__device__ __nv_bfloat16 g_dl[NW];
__device__ __nv_bfloat16 g_ih[(size_t)T_NUM * TOPK * I_DIM];
__device__ __nv_bfloat16 g_il[(size_t)T_NUM * TOPK * I_DIM];

// ---------------- helpers ----------------
__device__ __forceinline__ void cpa16(uint32_t dst, const void* src, int srcsz) {
    asm volatile("cp.async.cg.shared.global [%0], [%1], 16, %2;"
                 :: "r"(dst), "l"(src), "r"(srcsz) : "memory");
}
#define CP_COMMIT() asm volatile("cp.async.commit_group;" ::: "memory")
#define CP_WAIT1()  asm volatile("cp.async.wait_group 1;" ::: "memory")
#define CP_WAIT0()  asm volatile("cp.async.wait_group 0;" ::: "memory")

__device__ __forceinline__ uint32_t smem_u32(const void* p) {
    uint32_t a;
    asm("{ .reg .u64 t; cvta.to.shared.u64 t, %1; cvt.u32.u64 %0, t; }" : "=r"(a) : "l"(p));
    return a;
}

#define MMA(d, a, b0, b1) \
    asm volatile("mma.sync.aligned.m16n8k16.row.col.f32.bf16.bf16.f32 " \
        "{%0,%1,%2,%3}, {%4,%5,%6,%7}, {%8,%9}, {%0,%1,%2,%3};" \
        : "+f"((d)[0]), "+f"((d)[1]), "+f"((d)[2]), "+f"((d)[3]) \
        : "r"((a)[0]), "r"((a)[1]), "r"((a)[2]), "r"((a)[3]), "r"(b0), "r"(b1))

#define LDSM4(R, addr) \
    asm volatile("ldmatrix.sync.aligned.m8n8.x4.shared.b16 {%0,%1,%2,%3}, [%4];" \
        : "=r"((R)[0]), "=r"((R)[1]), "=r"((R)[2]), "=r"((R)[3]) : "r"(addr))

__device__ __forceinline__ uint32_t pack2(float v0, float v1, uint32_t& lo_out) {
    __nv_bfloat16 h0 = __float2bfloat16(v0);
    __nv_bfloat16 h1 = __float2bfloat16(v1);
    __nv_bfloat16 l0 = __float2bfloat16(v0 - __bfloat162float(h0));
    __nv_bfloat16 l1 = __float2bfloat16(v1 - __bfloat162float(h1));
    lo_out = (uint32_t)__bfloat16_as_ushort(l0) | ((uint32_t)__bfloat16_as_ushort(l1) << 16);
    return (uint32_t)__bfloat16_as_ushort(h0) | ((uint32_t)__bfloat16_as_ushort(h1) << 16);
}

// ---------------- conversion: fp32 -> (hi,lo) bf16 ----------------
// fused: blockIdx.y selects tensor (gate/up/down) — one launch for all weights
__global__ void __launch_bounds__(256)
convertw_kernel(const float* __restrict__ s0, __nv_bfloat16* __restrict__ h0, __nv_bfloat16* __restrict__ l0,
                const float* __restrict__ s1, __nv_bfloat16* __restrict__ h1, __nv_bfloat16* __restrict__ l1,
                const float* __restrict__ s2, __nv_bfloat16* __restrict__ h2, __nv_bfloat16* __restrict__ l2)
{
    const float* src = (blockIdx.y == 0) ? s0 : (blockIdx.y == 1) ? s1 : s2;
    __nv_bfloat16* hi = (blockIdx.y == 0) ? h0 : (blockIdx.y == 1) ? h1 : h2;
    __nv_bfloat16* lo = (blockIdx.y == 0) ? l0 : (blockIdx.y == 1) ? l1 : l2;
    size_t i = ((size_t)blockIdx.x * 256 + threadIdx.x) * 4;
    float4 v = *(const float4*)(src + i);
    uint32_t a01, a23;
    uint32_t b01 = pack2(v.x, v.y, a01);
    uint32_t b23 = pack2(v.z, v.w, a23);
    *(uint2*)(hi + i) = make_uint2(b01, b23);
    *(uint2*)(lo + i) = make_uint2(a01, a23);
}

__global__ void __launch_bounds__(256)
convert_kernel(const float* __restrict__ src,
               __nv_bfloat16* __restrict__ hi,
               __nv_bfloat16* __restrict__ lo, size_t n)
{
    size_t i = ((size_t)blockIdx.x * 256 + threadIdx.x) * 4;
    if (i >= n) return;
    float4 v = *(const float4*)(src + i);
    uint32_t l01, l23;
    uint32_t h01 = pack2(v.x, v.y, l01);
    uint32_t h23 = pack2(v.z, v.w, l23);
    *(uint2*)(hi + i) = make_uint2(h01, h23);
    *(uint2*)(lo + i) = make_uint2(l01, l23);
}

// ---------------- routing ----------------
__global__ void route_kernel(const unsigned* __restrict__ idx_raw,
                             const float* __restrict__ wts)
{
    __shared__ int s_flag;
    __shared__ int s_cnt[E_NUM];
    __shared__ int s_off[E_NUM + 1];
    const int tid = threadIdx.x, wid = tid >> 5, lane = tid & 31;

    if (tid == 0) s_flag = 0;
    __syncthreads();
    unsigned acc = 0;
    for (int i = 1 + 2 * tid; i < T_NUM * TOPK; i += 512) acc |= idx_raw[i];
    if (acc) atomicOr(&s_flag, 1);
    __syncthreads();
    const int is64 = (s_flag == 0) ? 1 : 0;

    const int e = wid;
    int c = 0;
    for (int base = 0; base < T_NUM; base += 32) {
        int t = base + lane;
        int e0 = is64 ? (int)idx_raw[4 * t]     : (int)idx_raw[2 * t];
        int e1 = is64 ? (int)idx_raw[4 * t + 2] : (int)idx_raw[2 * t + 1];
        c += (e0 == e || e1 == e) ? 1 : 0;
    }
#pragma unroll
    for (int o = 16; o; o >>= 1) c += __shfl_down_sync(0xffffffffu, c, o);
    if (lane == 0) s_cnt[e] = c;
    __syncthreads();
    if (tid == 0) {
        int o = 0;
        for (int i = 0; i < E_NUM; i++) { s_off[i] = o; g_off[i] = o; g_cnt[i] = s_cnt[i]; o += s_cnt[i]; }
        s_off[E_NUM] = o; g_off[E_NUM] = o;
    }
    __syncthreads();
    int p = s_off[e];
    for (int base = 0; base < T_NUM; base += 32) {
        int t = base + lane;
        int e0 = is64 ? (int)idx_raw[4 * t]     : (int)idx_raw[2 * t];
        int e1 = is64 ? (int)idx_raw[4 * t + 2] : (int)idx_raw[2 * t + 1];
        bool m = (e0 == e || e1 == e);
        float w = (e0 == e ? wts[2 * t] : 0.0f) + (e1 == e ? wts[2 * t + 1] : 0.0f);
        unsigned msk = __ballot_sync(0xffffffffu, m);
        int pos = p + __popc(msk & ((1u << lane) - 1u));
        if (m) { g_tok[pos] = t; g_wgt[pos] = w; }
        p += __popc(msk);
    }
}

// ---------------- GEMM1 (256 thr, 2 CTAs/SM, TN=64, 2-stage) ----------------
// stage: AH 0 (10240), AL 10240, GH 20480 (5120), GL 25600, UH 30720, UL 35840
#define ST1 40960
#define G1_SMEM (512 + 2 * ST1)     // 82432 -> 2 CTAs/SM

__global__ void __launch_bounds__(NTHREADS, 2)
gemm1_kernel()
{
    const int e = blockIdx.z;
    const int cnt = g_cnt[e];
    const int rowBase = blockIdx.x * TM;
    if (rowBase >= cnt) return;
    const int off = g_off[e];
    const int n0 = blockIdx.y * TN;

    extern __shared__ char smem[];
    int* s_tok = (int*)smem;
    const uint32_t sb = smem_u32(smem);

    const int tid = threadIdx.x, wid = tid >> 5, lane = tid & 31;
    const int wm = wid >> 1, wn = wid & 1;      // 4x2 warp grid, warp tile 32x32
    const int lr = lane >> 2, lc2 = (lane & 3) << 2;
    const int lg = lane >> 3, l7 = lane & 7;

    if (tid < TM) { int r = rowBase + tid; s_tok[tid] = (r < cnt) ? g_tok[off + r] : -1; }
    __syncthreads();

    // staging: ch = 16B chunk in row (0..3), rA = row (0..63; also +64 for A)
    const int ch = tid & 3, rA = tid >> 2;
    const int selem = ch * 8;
    const uint32_t d0 = sb + 512 + (uint32_t)(rA * RS + ch * 16);          // A row rA
    const uint32_t d1 = sb + 512 + (uint32_t)((rA + 64) * RS + ch * 16);   // A row rA+64
    const int tok0 = s_tok[rA], tok1 = s_tok[rA + 64];
    const int sz0 = (tok0 >= 0) ? 16 : 0, sz1 = (tok1 >= 0) ? 16 : 0;
    const size_t a0 = (size_t)(tok0 >= 0 ? tok0 : 0) * H_DIM + selem;
    const size_t a1 = (size_t)(tok1 >= 0 ? tok1 : 0) * H_DIM + selem;
    const size_t wrow = ((size_t)e * I_DIM + n0 + rA) * H_DIM + selem;     // weight row rA (0..63)

    const __nv_bfloat16 *xh0 = g_xh + a0, *xl0 = g_xl + a0;
    const __nv_bfloat16 *xh1 = g_xh + a1, *xl1 = g_xl + a1;
    const __nv_bfloat16 *wgh = g_gh + wrow, *wgl = g_gl + wrow;
    const __nv_bfloat16 *wuh = g_uh + wrow, *wul = g_ul + wrow;

    const uint32_t aoff = (uint32_t)((wm * 32 + ((lg & 1) << 3) + l7) * RS + ((lg >> 1) << 4));
    const uint32_t boff = (uint32_t)((wn * 32 + ((lg >> 1) << 3) + l7) * RS + ((lg & 1) << 4));

    float accG[2][4][4], accU[2][4][4];
#pragma unroll
    for (int i = 0; i < 2; i++)
#pragma unroll
        for (int j = 0; j < 4; j++)
#pragma unroll
            for (int k = 0; k < 4; k++) { accG[i][j][k] = 0.0f; accU[i][j][k] = 0.0f; }

    const int KB = H_DIM / TK;

#define G1_ISSUE(kb) do { \
        uint32_t s_ = (uint32_t)(((kb) & 1) * ST1); \
        int kk_ = (kb) * TK; \
        cpa16(d0 + s_,          xh0 + kk_, sz0); \
        cpa16(d1 + s_,          xh1 + kk_, sz1); \
        cpa16(d0 + s_ + 10240,  xl0 + kk_, sz0); \
        cpa16(d1 + s_ + 10240,  xl1 + kk_, sz1); \
        cpa16(d0 + s_ + 20480,  wgh + kk_, 16); \
        cpa16(d0 + s_ + 25600,  wgl + kk_, 16); \
        cpa16(d0 + s_ + 30720,  wuh + kk_, 16); \
        cpa16(d0 + s_ + 35840,  wul + kk_, 16); \
        CP_COMMIT(); \
    } while (0)

    G1_ISSUE(0);

    for (int kb = 0; kb < KB; kb++) {
        CP_WAIT0();
        __syncthreads();
        if (kb + 1 < KB) G1_ISSUE(kb + 1);

        const uint32_t s0 = sb + 512 + (uint32_t)((kb & 1) * ST1);
        const uint32_t sA = s0 + aoff;
        const uint32_t sB = s0 + boff;

#pragma unroll
        for (int k16 = 0; k16 < 2; k16++) {
            const uint32_t ka = (uint32_t)(k16 * 32);
            uint32_t aH[2][4], aL[2][4];
            LDSM4(aH[0], sA + ka);
            LDSM4(aH[1], sA + 16 * RS + ka);
            LDSM4(aL[0], sA + 10240 + ka);
            LDSM4(aL[1], sA + 10240 + 16 * RS + ka);
#pragma unroll
            for (int nt2 = 0; nt2 < 2; nt2++) {
                const uint32_t bn = sB + (uint32_t)(nt2 * 16 * RS) + ka;
                uint32_t b[4];
                // gate hi: aH + aL
                LDSM4(b, bn + 20480);
                MMA(accG[0][nt2 * 2 + 0], aH[0], b[0], b[1]);
                MMA(accG[0][nt2 * 2 + 1], aH[0], b[2], b[3]);
                MMA(accG[1][nt2 * 2 + 0], aH[1], b[0], b[1]);
                MMA(accG[1][nt2 * 2 + 1], aH[1], b[2], b[3]);
                MMA(accG[0][nt2 * 2 + 0], aL[0], b[0], b[1]);
                MMA(accG[0][nt2 * 2 + 1], aL[0], b[2], b[3]);
                MMA(accG[1][nt2 * 2 + 0], aL[1], b[0], b[1]);
                MMA(accG[1][nt2 * 2 + 1], aL[1], b[2], b[3]);
                // gate lo: aH only
                LDSM4(b, bn + 25600);
                MMA(accG[0][nt2 * 2 + 0], aH[0], b[0], b[1]);
                MMA(accG[0][nt2 * 2 + 1], aH[0], b[2], b[3]);
                MMA(accG[1][nt2 * 2 + 0], aH[1], b[0], b[1]);
                MMA(accG[1][nt2 * 2 + 1], aH[1], b[2], b[3]);
                // up hi: aH + aL
                LDSM4(b, bn + 30720);
                MMA(accU[0][nt2 * 2 + 0], aH[0], b[0], b[1]);
                MMA(accU[0][nt2 * 2 + 1], aH[0], b[2], b[3]);
                MMA(accU[1][nt2 * 2 + 0], aH[1], b[0], b[1]);
                MMA(accU[1][nt2 * 2 + 1], aH[1], b[2], b[3]);
                MMA(accU[0][nt2 * 2 + 0], aL[0], b[0], b[1]);
                MMA(accU[0][nt2 * 2 + 1], aL[0], b[2], b[3]);
                MMA(accU[1][nt2 * 2 + 0], aL[1], b[0], b[1]);
                MMA(accU[1][nt2 * 2 + 1], aL[1], b[2], b[3]);
                // up lo: aH only
                LDSM4(b, bn + 35840);
                MMA(accU[0][nt2 * 2 + 0], aH[0], b[0], b[1]);
                MMA(accU[0][nt2 * 2 + 1], aH[0], b[2], b[3]);
                MMA(accU[1][nt2 * 2 + 0], aH[1], b[0], b[1]);
                MMA(accU[1][nt2 * 2 + 1], aH[1], b[2], b[3]);
            }
        }
    }
#undef G1_ISSUE

    // epilogue: silu(g)*u -> inter hi/lo
#pragma unroll
    for (int mt = 0; mt < 2; mt++) {
#pragma unroll
        for (int half = 0; half < 2; half++) {
            int rloc = wm * 32 + mt * 16 + lr + half * 8;
            int r = rowBase + rloc;
            if (r >= cnt) continue;
            size_t base = (size_t)(off + r) * I_DIM + n0 + wn * 32 + (lc2 >> 1);
#pragma unroll
            for (int nt = 0; nt < 4; nt++) {
                float g0 = accG[mt][nt][half * 2 + 0], u0 = accU[mt][nt][half * 2 + 0];
                float g1 = accG[mt][nt][half * 2 + 1], u1 = accU[mt][nt][half * 2 + 1];
                float v0 = (g0 / (1.0f + __expf(-g0))) * u0;
                float v1 = (g1 / (1.0f + __expf(-g1))) * u1;
                uint32_t lo;
                uint32_t hi = pack2(v0, v1, lo);
                *(uint32_t*)(g_ih + base + nt * 8) = hi;
                *(uint32_t*)(g_il + base + nt * 8) = lo;
            }
        }
    }
}

// ---------------- GEMM2 (256 thr, 2 CTAs/SM, TN=64, 3-stage) ----------------
// stage: AH 0 (10240), AL 10240, BH 20480 (5120), BL 25600
#define ST2 30720
#define G2_SMEM (1024 + 3 * ST2)    // 93184 -> 2 CTAs/SM

__global__ void __launch_bounds__(NTHREADS, 2)
gemm2_kernel(float* __restrict__ out)
{
    const int e = blockIdx.z;
    const int cnt = g_cnt[e];
    const int rowBase = blockIdx.x * TM;
    if (rowBase >= cnt) return;
    const int off = g_off[e];
    const int n0 = blockIdx.y * TN;

    extern __shared__ char smem[];
    int*   s_tok = (int*)smem;
    float* s_wgt = (float*)(smem + 512);
    const uint32_t sb = smem_u32(smem);

    const int tid = threadIdx.x, wid = tid >> 5, lane = tid & 31;
    const int wm = wid >> 1, wn = wid & 1;
    const int lr = lane >> 2, lc2 = (lane & 3) << 2;
    const int lg = lane >> 3, l7 = lane & 7;

    if (tid < TM) {
        int r = rowBase + tid;
        s_tok[tid] = (r < cnt) ? g_tok[off + r] : -1;
        s_wgt[tid] = (r < cnt) ? g_wgt[off + r] : 0.0f;
    }
    __syncthreads();

    const int ch = tid & 3, rA = tid >> 2;
    const int selem = ch * 8;
    const uint32_t d0 = sb + 1024 + (uint32_t)(rA * RS + ch * 16);
    const uint32_t d1 = sb + 1024 + (uint32_t)((rA + 64) * RS + ch * 16);
    const int v0ok = (rowBase + rA < cnt), v1ok = (rowBase + rA + 64 < cnt);
    const int sz0 = v0ok ? 16 : 0, sz1 = v1ok ? 16 : 0;
    const size_t a0 = (size_t)(off + (v0ok ? rowBase + rA : 0)) * I_DIM + selem;
    const size_t a1 = (size_t)(off + (v1ok ? rowBase + rA + 64 : 0)) * I_DIM + selem;
    const size_t brow = ((size_t)e * H_DIM + n0 + rA) * I_DIM + selem;

    const __nv_bfloat16 *ih0 = g_ih + a0, *il0 = g_il + a0;
    const __nv_bfloat16 *ih1 = g_ih + a1, *il1 = g_il + a1;
    const __nv_bfloat16 *bdh = g_dh + brow, *bdl = g_dl + brow;

    const uint32_t aoff = (uint32_t)((wm * 32 + ((lg & 1) << 3) + l7) * RS + ((lg >> 1) << 4));
    const uint32_t boff = (uint32_t)((wn * 32 + ((lg >> 1) << 3) + l7) * RS + ((lg & 1) << 4));

    float acc[2][4][4];
#pragma unroll
    for (int i = 0; i < 2; i++)
#pragma unroll
        for (int j = 0; j < 4; j++)
#pragma unroll
            for (int k = 0; k < 4; k++) acc[i][j][k] = 0.0f;

    const int KB = I_DIM / TK;

#define G2_ISSUE(kb) do { \
        uint32_t s_ = (uint32_t)(((kb) % 3) * ST2); \
        int kk_ = (kb) * TK; \
        cpa16(d0 + s_,         ih0 + kk_, sz0); \
        cpa16(d1 + s_,         ih1 + kk_, sz1); \
        cpa16(d0 + s_ + 10240, il0 + kk_, sz0); \
        cpa16(d1 + s_ + 10240, il1 + kk_, sz1); \
        cpa16(d0 + s_ + 20480, bdh + kk_, 16); \
        cpa16(d0 + s_ + 25600, bdl + kk_, 16); \
        CP_COMMIT(); \
    } while (0)

    G2_ISSUE(0);
    G2_ISSUE(1);

    for (int kb = 0; kb < KB; kb++) {
        if (kb + 1 < KB) { CP_WAIT1(); } else { CP_WAIT0(); }
        __syncthreads();
        if (kb + 2 < KB) G2_ISSUE(kb + 2);

        const uint32_t s0 = sb + 1024 + (uint32_t)((kb % 3) * ST2);
        const uint32_t sA = s0 + aoff;
        const uint32_t sB = s0 + boff;

#pragma unroll
        for (int k16 = 0; k16 < 2; k16++) {
            const uint32_t ka = (uint32_t)(k16 * 32);
            uint32_t aH[2][4], aL[2][4];
            LDSM4(aH[0], sA + ka);
            LDSM4(aH[1], sA + 16 * RS + ka);
            LDSM4(aL[0], sA + 10240 + ka);
            LDSM4(aL[1], sA + 10240 + 16 * RS + ka);
#pragma unroll
            for (int nt2 = 0; nt2 < 2; nt2++) {
                const uint32_t bn = sB + (uint32_t)(nt2 * 16 * RS) + ka;
                uint32_t b[4];
                // down hi: aH + aL
                LDSM4(b, bn + 20480);
                MMA(acc[0][nt2 * 2 + 0], aH[0], b[0], b[1]);
                MMA(acc[0][nt2 * 2 + 1], aH[0], b[2], b[3]);
                MMA(acc[1][nt2 * 2 + 0], aH[1], b[0], b[1]);
                MMA(acc[1][nt2 * 2 + 1], aH[1], b[2], b[3]);
                MMA(acc[0][nt2 * 2 + 0], aL[0], b[0], b[1]);
                MMA(acc[0][nt2 * 2 + 1], aL[0], b[2], b[3]);
                MMA(acc[1][nt2 * 2 + 0], aL[1], b[0], b[1]);
                MMA(acc[1][nt2 * 2 + 1], aL[1], b[2], b[3]);
                // down lo: aH only
                LDSM4(b, bn + 25600);
                MMA(acc[0][nt2 * 2 + 0], aH[0], b[0], b[1]);
                MMA(acc[0][nt2 * 2 + 1], aH[0], b[2], b[3]);
                MMA(acc[1][nt2 * 2 + 0], aH[1], b[0], b[1]);
                MMA(acc[1][nt2 * 2 + 1], aH[1], b[2], b[3]);
            }
        }
    }
#undef G2_ISSUE

    // epilogue: weighted scatter-add
#pragma unroll
    for (int mt = 0; mt < 2; mt++) {
#pragma unroll
        for (int half = 0; half < 2; half++) {
            int rloc = wm * 32 + mt * 16 + lr + half * 8;
            int t = s_tok[rloc];
            if (t < 0) continue;
            float w = s_wgt[rloc];
            float* dst = out + (size_t)t * H_DIM + n0 + wn * 32 + (lc2 >> 1);
#pragma unroll
            for (int nt = 0; nt < 4; nt++) {
                atomicAdd(dst + nt * 8 + 0, w * acc[mt][nt][half * 2 + 0]);
                atomicAdd(dst + nt * 8 + 1, w * acc[mt][nt][half * 2 + 1]);
            }
        }
    }
}

// ---------------- launch ----------------
extern "C" void kernel_launch(void* const* d_in, const int* in_sizes, int n_in,
                              void* d_out, int out_size)
{
    const float*    x    = (const float*)d_in[0];
    const unsigned* idx  = (const unsigned*)d_in[1];
    const float*    wts  = (const float*)d_in[2];
    const float*    gate = (const float*)d_in[3];
    const float*    up   = (const float*)d_in[4];
    const float*    down = (const float*)d_in[5];
    float* out = (float*)d_out;

    static int attr_done = 0;
    if (!attr_done) {
        cudaFuncSetAttribute(gemm1_kernel, cudaFuncAttributeMaxDynamicSharedMemorySize, G1_SMEM);
        cudaFuncSetAttribute(gemm2_kernel, cudaFuncAttributeMaxDynamicSharedMemorySize, G2_SMEM);
        attr_done = 1;
    }

    cudaMemsetAsync(out, 0, (size_t)out_size * sizeof(float));
    route_kernel<<<1, 256>>>(idx, wts);

    __nv_bfloat16 *gh, *gl, *uh, *ul, *dh, *dl, *xh, *xl;
    cudaGetSymbolAddress((void**)&gh, g_gh); cudaGetSymbolAddress((void**)&gl, g_gl);
    cudaGetSymbolAddress((void**)&uh, g_uh); cudaGetSymbolAddress((void**)&ul, g_ul);
    cudaGetSymbolAddress((void**)&dh, g_dh); cudaGetSymbolAddress((void**)&dl, g_dl);
    cudaGetSymbolAddress((void**)&xh, g_xh); cudaGetSymbolAddress((void**)&xl, g_xl);

    const size_t nw = NW;
    const size_t nx = (size_t)T_NUM * H_DIM;
    convertw_kernel<<<dim3((unsigned)(nw / 1024), 3), 256>>>(gate, gh, gl, up, uh, ul, down, dh, dl);
    convert_kernel<<<(unsigned)(nx / 1024), 256>>>(x, xh, xl, nx);

    gemm1_kernel<<<dim3(T_NUM / TM, I_DIM / TN, E_NUM), NTHREADS, G1_SMEM>>>();
    gemm2_kernel<<<dim3(T_NUM / TM, H_DIM / TN, E_NUM), NTHREADS, G2_SMEM>>>(out);
}

// round 10
// speedup vs baseline: 1.0191x; 1.0191x over previous
#include <cuda_runtime.h>
#include <cuda_bf16.h>
#include <stdint.h>

// ---------------- problem constants ----------------
#define H_DIM 2048
#define I_DIM 4096
#define E_NUM 8
#define T_NUM 4096   // B*S
#define TOPK  2

#define TM 128
#define TN 128
#define TK 32
#define NTHREADS 512
#define RS 80        // SMEM row stride bytes (32 bf16 = 64B + 16B pad)
#define NSTAGE 3

// ---------------- scratch (__device__ globals: allocation-free) ----------------
__device__ int   g_tok[T_NUM * TOPK];
__device__ float g_wgt[T_NUM * TOPK];
__device__ int   g_cnt[E_NUM];
__device__ int   g_off[E_NUM + 1];

#define NW ((size_t)E_NUM * I_DIM * H_DIM)
__device__ __nv_bfloat16 g_xh[(size_t)T_NUM * H_DIM];
__device__ __nv_bfloat16 g_xl[(size_t)T_NUM * H_DIM];
__device__ __nv_bfloat16 g_gh[NW];
__device__ __nv_bfloat16 g_gl[NW];
__device__ __nv_bfloat16 g_uh[NW];
__device__ __nv_bfloat16 g_ul[NW];
__device__ __nv_bfloat16 g_dh[NW];
__device__ __nv_bfloat16 g_dl[NW];
__device__ __nv_bfloat16 g_ih[(size_t)T_NUM * TOPK * I_DIM];
__device__ __nv_bfloat16 g_il[(size_t)T_NUM * TOPK * I_DIM];

// ---------------- helpers ----------------
__device__ __forceinline__ void cpa16(uint32_t dst, const void* src, int srcsz) {
    asm volatile("cp.async.cg.shared.global [%0], [%1], 16, %2;"
                 :: "r"(dst), "l"(src), "r"(srcsz) : "memory");
}
#define CP_COMMIT() asm volatile("cp.async.commit_group;" ::: "memory")
#define CP_WAIT1()  asm volatile("cp.async.wait_group 1;" ::: "memory")
#define CP_WAIT0()  asm volatile("cp.async.wait_group 0;" ::: "memory")

__device__ __forceinline__ uint32_t smem_u32(const void* p) {
    uint32_t a;
    asm("{ .reg .u64 t; cvta.to.shared.u64 t, %1; cvt.u32.u64 %0, t; }" : "=r"(a) : "l"(p));
    return a;
}

#define MMA(d, a, b0, b1) \
    asm volatile("mma.sync.aligned.m16n8k16.row.col.f32.bf16.bf16.f32 " \
        "{%0,%1,%2,%3}, {%4,%5,%6,%7}, {%8,%9}, {%0,%1,%2,%3};" \
        : "+f"((d)[0]), "+f"((d)[1]), "+f"((d)[2]), "+f"((d)[3]) \
        : "r"((a)[0]), "r"((a)[1]), "r"((a)[2]), "r"((a)[3]), "r"(b0), "r"(b1))

#define LDSM4(R, addr) \
    asm volatile("ldmatrix.sync.aligned.m8n8.x4.shared.b16 {%0,%1,%2,%3}, [%4];" \
        : "=r"((R)[0]), "=r"((R)[1]), "=r"((R)[2]), "=r"((R)[3]) : "r"(addr))

__device__ __forceinline__ uint32_t pack2(float v0, float v1, uint32_t& lo_out) {
    __nv_bfloat16 h0 = __float2bfloat16(v0);
    __nv_bfloat16 h1 = __float2bfloat16(v1);
    __nv_bfloat16 l0 = __float2bfloat16(v0 - __bfloat162float(h0));
    __nv_bfloat16 l1 = __float2bfloat16(v1 - __bfloat162float(h1));
    lo_out = (uint32_t)__bfloat16_as_ushort(l0) | ((uint32_t)__bfloat16_as_ushort(l1) << 16);
    return (uint32_t)__bfloat16_as_ushort(h0) | ((uint32_t)__bfloat16_as_ushort(h1) << 16);
}

// ---------------- conversion: fp32 -> (hi,lo) bf16 ----------------
__global__ void __launch_bounds__(256)
convertw_kernel(const float* __restrict__ s0, __nv_bfloat16* __restrict__ h0, __nv_bfloat16* __restrict__ l0,
                const float* __restrict__ s1, __nv_bfloat16* __restrict__ h1, __nv_bfloat16* __restrict__ l1,
                const float* __restrict__ s2, __nv_bfloat16* __restrict__ h2, __nv_bfloat16* __restrict__ l2)
{
    const float* src = (blockIdx.y == 0) ? s0 : (blockIdx.y == 1) ? s1 : s2;
    __nv_bfloat16* hi = (blockIdx.y == 0) ? h0 : (blockIdx.y == 1) ? h1 : h2;
    __nv_bfloat16* lo = (blockIdx.y == 0) ? l0 : (blockIdx.y == 1) ? l1 : l2;
    size_t i = ((size_t)blockIdx.x * 256 + threadIdx.x) * 4;
    float4 v = *(const float4*)(src + i);
    uint32_t a01, a23;
    uint32_t b01 = pack2(v.x, v.y, a01);
    uint32_t b23 = pack2(v.z, v.w, a23);
    *(uint2*)(hi + i) = make_uint2(b01, b23);
    *(uint2*)(lo + i) = make_uint2(a01, a23);
}

__global__ void __launch_bounds__(256)
convert_kernel(const float* __restrict__ src,
               __nv_bfloat16* __restrict__ hi,
               __nv_bfloat16* __restrict__ lo, size_t n)
{
    size_t i = ((size_t)blockIdx.x * 256 + threadIdx.x) * 4;
    if (i >= n) return;
    float4 v = *(const float4*)(src + i);
    uint32_t l01, l23;
    uint32_t h01 = pack2(v.x, v.y, l01);
    uint32_t h23 = pack2(v.z, v.w, l23);
    *(uint2*)(hi + i) = make_uint2(h01, h23);
    *(uint2*)(lo + i) = make_uint2(l01, l23);
}

// ---------------- routing ----------------
__global__ void route_kernel(const unsigned* __restrict__ idx_raw,
                             const float* __restrict__ wts)
{
    __shared__ int s_flag;
    __shared__ int s_cnt[E_NUM];
    __shared__ int s_off[E_NUM + 1];
    const int tid = threadIdx.x, wid = tid >> 5, lane = tid & 31;

    if (tid == 0) s_flag = 0;
    __syncthreads();
    unsigned acc = 0;
    for (int i = 1 + 2 * tid; i < T_NUM * TOPK; i += 512) acc |= idx_raw[i];
    if (acc) atomicOr(&s_flag, 1);
    __syncthreads();
    const int is64 = (s_flag == 0) ? 1 : 0;

    const int e = wid;
    int c = 0;
    for (int base = 0; base < T_NUM; base += 32) {
        int t = base + lane;
        int e0 = is64 ? (int)idx_raw[4 * t]     : (int)idx_raw[2 * t];
        int e1 = is64 ? (int)idx_raw[4 * t + 2] : (int)idx_raw[2 * t + 1];
        c += (e0 == e || e1 == e) ? 1 : 0;
    }
#pragma unroll
    for (int o = 16; o; o >>= 1) c += __shfl_down_sync(0xffffffffu, c, o);
    if (lane == 0) s_cnt[e] = c;
    __syncthreads();
    if (tid == 0) {
        int o = 0;
        for (int i = 0; i < E_NUM; i++) { s_off[i] = o; g_off[i] = o; g_cnt[i] = s_cnt[i]; o += s_cnt[i]; }
        s_off[E_NUM] = o; g_off[E_NUM] = o;
    }
    __syncthreads();
    int p = s_off[e];
    for (int base = 0; base < T_NUM; base += 32) {
        int t = base + lane;
        int e0 = is64 ? (int)idx_raw[4 * t]     : (int)idx_raw[2 * t];
        int e1 = is64 ? (int)idx_raw[4 * t + 2] : (int)idx_raw[2 * t + 1];
        bool m = (e0 == e || e1 == e);
        float w = (e0 == e ? wts[2 * t] : 0.0f) + (e1 == e ? wts[2 * t + 1] : 0.0f);
        unsigned msk = __ballot_sync(0xffffffffu, m);
        int pos = p + __popc(msk & ((1u << lane) - 1u));
        if (m) { g_tok[pos] = t; g_wgt[pos] = w; }
        p += __popc(msk);
    }
}

// ---------------- GEMM1 (512 thr, TN=128, 3-stage, distance-8 MMA schedule) ----------------
// stage tiles: AH 0, AL 10240, GH 20480, GL 30720, UH 40960, UL 51200
#define ST1 (6 * TM * RS)                 // 61440
#define G1_SMEM (512 + NSTAGE * ST1)      // 184832

__global__ void __launch_bounds__(NTHREADS, 1)
gemm1_kernel()
{
    const int e = blockIdx.z;
    const int cnt = g_cnt[e];
    const int rowBase = blockIdx.x * TM;
    if (rowBase >= cnt) return;
    const int off = g_off[e];
    const int n0 = blockIdx.y * TN;

    extern __shared__ char smem[];
    int* s_tok = (int*)smem;
    const uint32_t sb = smem_u32(smem);

    const int tid = threadIdx.x, wid = tid >> 5, lane = tid & 31;
    const int wm = wid >> 2, wn = wid & 3;
    const int lr = lane >> 2, lc2 = (lane & 3) << 2;
    const int lg = lane >> 3, l7 = lane & 7;

    if (tid < TM) { int r = rowBase + tid; s_tok[tid] = (r < cnt) ? g_tok[off + r] : -1; }
    __syncthreads();

    const int srow = tid >> 2, sch = tid & 3;
    const int selem = sch * 8;
    const uint32_t sdst = sb + 512 + (uint32_t)(srow * RS + sch * 16);
    const int stok = s_tok[srow];
    const int asz = (stok >= 0) ? 16 : 0;
    const size_t arow = (size_t)(stok >= 0 ? stok : 0) * H_DIM + selem;
    const size_t wrow = ((size_t)e * I_DIM + n0 + srow) * H_DIM + selem;
    const __nv_bfloat16* axh = g_xh + arow;
    const __nv_bfloat16* axl = g_xl + arow;
    const __nv_bfloat16* agh = g_gh + wrow;
    const __nv_bfloat16* agl = g_gl + wrow;
    const __nv_bfloat16* auh = g_uh + wrow;
    const __nv_bfloat16* aul = g_ul + wrow;

    const uint32_t aoff = (uint32_t)((wm * 32 + ((lg & 1) << 3) + l7) * RS + ((lg >> 1) << 4));
    const uint32_t boff = (uint32_t)((wn * 32 + ((lg >> 1) << 3) + l7) * RS + ((lg & 1) << 4));

    float accG[2][4][4], accU[2][4][4];
#pragma unroll
    for (int i = 0; i < 2; i++)
#pragma unroll
        for (int j = 0; j < 4; j++)
#pragma unroll
            for (int k = 0; k < 4; k++) { accG[i][j][k] = 0.0f; accU[i][j][k] = 0.0f; }

    const int KB = H_DIM / TK;

#define G1_ISSUE(kb, st) do { \
        uint32_t b_ = sdst + (uint32_t)(st) * ST1; \
        int kk_ = (kb) * TK; \
        cpa16(b_ +     0, axh + kk_, asz); \
        cpa16(b_ + 10240, axl + kk_, asz); \
        cpa16(b_ + 20480, agh + kk_, 16); \
        cpa16(b_ + 30720, agl + kk_, 16); \
        cpa16(b_ + 40960, auh + kk_, 16); \
        cpa16(b_ + 51200, aul + kk_, 16); \
        CP_COMMIT(); \
    } while (0)

    G1_ISSUE(0, 0);
    G1_ISSUE(1, 1);

    for (int kb = 0; kb < KB; kb++) {
        if (kb + 1 < KB) { CP_WAIT1(); } else { CP_WAIT0(); }
        __syncthreads();
        if (kb + 2 < KB) G1_ISSUE(kb + 2, (kb + 2) % NSTAGE);

        const uint32_t s0 = sb + 512 + (uint32_t)((kb % NSTAGE) * ST1);
        const uint32_t sA = s0 + aoff;
        const uint32_t sB = s0 + boff;

#pragma unroll
        for (int k16 = 0; k16 < 2; k16++) {
            const uint32_t ka = (uint32_t)(k16 * 32);
            uint32_t aH[2][4], aL[2][4];
            LDSM4(aH[0], sA + ka);
            LDSM4(aH[1], sA + 16 * RS + ka);
            LDSM4(aL[0], sA + 10240 + ka);
            LDSM4(aL[1], sA + 10240 + 16 * RS + ka);
#pragma unroll
            for (int nt2 = 0; nt2 < 2; nt2++) {
                const uint32_t bn = sB + (uint32_t)(nt2 * 16 * RS) + ka;
                const int p = nt2 * 2, q = nt2 * 2 + 1;
                uint32_t bg[4], bu[4];
                LDSM4(bg, bn + 20480);      // gate hi
                LDSM4(bu, bn + 40960);      // up hi
                // batch 1: aH x gate-hi (4 distinct accs)
                MMA(accG[0][p], aH[0], bg[0], bg[1]);
                MMA(accG[0][q], aH[0], bg[2], bg[3]);
                MMA(accG[1][p], aH[1], bg[0], bg[1]);
                MMA(accG[1][q], aH[1], bg[2], bg[3]);
                // batch 2: aH x up-hi (4 distinct accs)
                MMA(accU[0][p], aH[0], bu[0], bu[1]);
                MMA(accU[0][q], aH[0], bu[2], bu[3]);
                MMA(accU[1][p], aH[1], bu[0], bu[1]);
                MMA(accU[1][q], aH[1], bu[2], bu[3]);
                // batch 3: aL x gate-hi (distance 8 from batch 1)
                MMA(accG[0][p], aL[0], bg[0], bg[1]);
                MMA(accG[0][q], aL[0], bg[2], bg[3]);
                MMA(accG[1][p], aL[1], bg[0], bg[1]);
                MMA(accG[1][q], aL[1], bg[2], bg[3]);
                // batch 4: aL x up-hi (distance 8 from batch 2)
                MMA(accU[0][p], aL[0], bu[0], bu[1]);
                MMA(accU[0][q], aL[0], bu[2], bu[3]);
                MMA(accU[1][p], aL[1], bu[0], bu[1]);
                MMA(accU[1][q], aL[1], bu[2], bu[3]);
                uint32_t bgl[4], bul[4];
                LDSM4(bgl, bn + 30720);     // gate lo
                LDSM4(bul, bn + 51200);     // up lo
                // batch 5: aH x gate-lo (distance 8 from batch 3)
                MMA(accG[0][p], aH[0], bgl[0], bgl[1]);
                MMA(accG[0][q], aH[0], bgl[2], bgl[3]);
                MMA(accG[1][p], aH[1], bgl[0], bgl[1]);
                MMA(accG[1][q], aH[1], bgl[2], bgl[3]);
                // batch 6: aH x up-lo (distance 8 from batch 4)
                MMA(accU[0][p], aH[0], bul[0], bul[1]);
                MMA(accU[0][q], aH[0], bul[2], bul[3]);
                MMA(accU[1][p], aH[1], bul[0], bul[1]);
                MMA(accU[1][q], aH[1], bul[2], bul[3]);
            }
        }
    }
#undef G1_ISSUE

    // epilogue: silu(g)*u -> inter hi/lo
#pragma unroll
    for (int mt = 0; mt < 2; mt++) {
#pragma unroll
        for (int half = 0; half < 2; half++) {
            int rloc = wm * 32 + mt * 16 + lr + half * 8;
            int r = rowBase + rloc;
            if (r >= cnt) continue;
            size_t base = (size_t)(off + r) * I_DIM + n0 + wn * 32 + (lc2 >> 1);
#pragma unroll
            for (int nt = 0; nt < 4; nt++) {
                float g0 = accG[mt][nt][half * 2 + 0], u0 = accU[mt][nt][half * 2 + 0];
                float g1 = accG[mt][nt][half * 2 + 1], u1 = accU[mt][nt][half * 2 + 1];
                float v0 = (g0 / (1.0f + __expf(-g0))) * u0;
                float v1 = (g1 / (1.0f + __expf(-g1))) * u1;
                uint32_t lo;
                uint32_t hi = pack2(v0, v1, lo);
                *(uint32_t*)(g_ih + base + nt * 8) = hi;
                *(uint32_t*)(g_il + base + nt * 8) = lo;
            }
        }
    }
}

// ---------------- GEMM2 (512 thr, TN=128, 3-stage, distance-8 MMA schedule) ----------------
// stage tiles: AH 0, AL 10240, BH 20480, BL 30720
#define ST2 (4 * TM * RS)                 // 40960
#define G2_SMEM (1024 + NSTAGE * ST2)     // 123904

__global__ void __launch_bounds__(NTHREADS, 1)
gemm2_kernel(float* __restrict__ out)
{
    const int e = blockIdx.z;
    const int cnt = g_cnt[e];
    const int rowBase = blockIdx.x * TM;
    if (rowBase >= cnt) return;
    const int off = g_off[e];
    const int n0 = blockIdx.y * TN;

    extern __shared__ char smem[];
    int*   s_tok = (int*)smem;
    float* s_wgt = (float*)(smem + 512);
    const uint32_t sb = smem_u32(smem);

    const int tid = threadIdx.x, wid = tid >> 5, lane = tid & 31;
    const int wm = wid >> 2, wn = wid & 3;
    const int lr = lane >> 2, lc2 = (lane & 3) << 2;
    const int lg = lane >> 3, l7 = lane & 7;

    if (tid < TM) {
        int r = rowBase + tid;
        s_tok[tid] = (r < cnt) ? g_tok[off + r] : -1;
        s_wgt[tid] = (r < cnt) ? g_wgt[off + r] : 0.0f;
    }
    __syncthreads();

    const int srow = tid >> 2, sch = tid & 3;
    const int selem = sch * 8;
    const uint32_t sdst = sb + 1024 + (uint32_t)(srow * RS + sch * 16);
    const int valid = (rowBase + srow < cnt);
    const int asz = valid ? 16 : 0;
    const size_t arow = (size_t)(off + (valid ? rowBase + srow : 0)) * I_DIM + selem;
    const size_t brow = ((size_t)e * H_DIM + n0 + srow) * I_DIM + selem;
    const __nv_bfloat16* aih = g_ih + arow;
    const __nv_bfloat16* ail = g_il + arow;
    const __nv_bfloat16* adh = g_dh + brow;
    const __nv_bfloat16* adl = g_dl + brow;

    const uint32_t aoff = (uint32_t)((wm * 32 + ((lg & 1) << 3) + l7) * RS + ((lg >> 1) << 4));
    const uint32_t boff = (uint32_t)((wn * 32 + ((lg >> 1) << 3) + l7) * RS + ((lg & 1) << 4));

    float acc[2][4][4];
#pragma unroll
    for (int i = 0; i < 2; i++)
#pragma unroll
        for (int j = 0; j < 4; j++)
#pragma unroll
            for (int k = 0; k < 4; k++) acc[i][j][k] = 0.0f;

    const int KB = I_DIM / TK;

#define G2_ISSUE(kb, st) do { \
        uint32_t b_ = sdst + (uint32_t)(st) * ST2; \
        int kk_ = (kb) * TK; \
        cpa16(b_ +     0, aih + kk_, asz); \
        cpa16(b_ + 10240, ail + kk_, asz); \
        cpa16(b_ + 20480, adh + kk_, 16); \
        cpa16(b_ + 30720, adl + kk_, 16); \
        CP_COMMIT(); \
    } while (0)

    G2_ISSUE(0, 0);
    G2_ISSUE(1, 1);

    for (int kb = 0; kb < KB; kb++) {
        if (kb + 1 < KB) { CP_WAIT1(); } else { CP_WAIT0(); }
        __syncthreads();
        if (kb + 2 < KB) G2_ISSUE(kb + 2, (kb + 2) % NSTAGE);

        const uint32_t s0 = sb + 1024 + (uint32_t)((kb % NSTAGE) * ST2);
        const uint32_t sA = s0 + aoff;
        const uint32_t sB = s0 + boff;

#pragma unroll
        for (int k16 = 0; k16 < 2; k16++) {
            const uint32_t ka = (uint32_t)(k16 * 32);
            uint32_t aH[2][4], aL[2][4];
            LDSM4(aH[0], sA + ka);
            LDSM4(aH[1], sA + 16 * RS + ka);
            LDSM4(aL[0], sA + 10240 + ka);
            LDSM4(aL[1], sA + 10240 + 16 * RS + ka);

            uint32_t b0h[4], b1h[4];
            LDSM4(b0h, sB + ka + 20480);                          // down hi, nt2=0
            LDSM4(b1h, sB + (uint32_t)(16 * RS) + ka + 20480);    // down hi, nt2=1
            // batch 1: aH x b0h -> accs {0,1}x{0,1}
            MMA(acc[0][0], aH[0], b0h[0], b0h[1]);
            MMA(acc[0][1], aH[0], b0h[2], b0h[3]);
            MMA(acc[1][0], aH[1], b0h[0], b0h[1]);
            MMA(acc[1][1], aH[1], b0h[2], b0h[3]);
            // batch 2: aH x b1h -> accs {0,1}x{2,3}
            MMA(acc[0][2], aH[0], b1h[0], b1h[1]);
            MMA(acc[0][3], aH[0], b1h[2], b1h[3]);
            MMA(acc[1][2], aH[1], b1h[0], b1h[1]);
            MMA(acc[1][3], aH[1], b1h[2], b1h[3]);
            // batch 3: aL x b0h (distance 8 from batch 1)
            MMA(acc[0][0], aL[0], b0h[0], b0h[1]);
            MMA(acc[0][1], aL[0], b0h[2], b0h[3]);
            MMA(acc[1][0], aL[1], b0h[0], b0h[1]);
            MMA(acc[1][1], aL[1], b0h[2], b0h[3]);
            // batch 4: aL x b1h (distance 8 from batch 2)
            MMA(acc[0][2], aL[0], b1h[0], b1h[1]);
            MMA(acc[0][3], aL[0], b1h[2], b1h[3]);
            MMA(acc[1][2], aL[1], b1h[0], b1h[1]);
            MMA(acc[1][3], aL[1], b1h[2], b1h[3]);

            uint32_t b0l[4], b1l[4];
            LDSM4(b0l, sB + ka + 30720);                          // down lo, nt2=0
            LDSM4(b1l, sB + (uint32_t)(16 * RS) + ka + 30720);    // down lo, nt2=1
            // batch 5: aH x b0l (distance 8 from batch 3)
            MMA(acc[0][0], aH[0], b0l[0], b0l[1]);
            MMA(acc[0][1], aH[0], b0l[2], b0l[3]);
            MMA(acc[1][0], aH[1], b0l[0], b0l[1]);
            MMA(acc[1][1], aH[1], b0l[2], b0l[3]);
            // batch 6: aH x b1l (distance 8 from batch 4)
            MMA(acc[0][2], aH[0], b1l[0], b1l[1]);
            MMA(acc[0][3], aH[0], b1l[2], b1l[3]);
            MMA(acc[1][2], aH[1], b1l[0], b1l[1]);
            MMA(acc[1][3], aH[1], b1l[2], b1l[3]);
        }
    }
#undef G2_ISSUE

    // epilogue: weighted scatter-add
#pragma unroll
    for (int mt = 0; mt < 2; mt++) {
#pragma unroll
        for (int half = 0; half < 2; half++) {
            int rloc = wm * 32 + mt * 16 + lr + half * 8;
            int t = s_tok[rloc];
            if (t < 0) continue;
            float w = s_wgt[rloc];
            float* dst = out + (size_t)t * H_DIM + n0 + wn * 32 + (lc2 >> 1);
#pragma unroll
            for (int nt = 0; nt < 4; nt++) {
                atomicAdd(dst + nt * 8 + 0, w * acc[mt][nt][half * 2 + 0]);
                atomicAdd(dst + nt * 8 + 1, w * acc[mt][nt][half * 2 + 1]);
            }
        }
    }
}

// ---------------- launch ----------------
extern "C" void kernel_launch(void* const* d_in, const int* in_sizes, int n_in,
                              void* d_out, int out_size)
{
    const float*    x    = (const float*)d_in[0];
    const unsigned* idx  = (const unsigned*)d_in[1];
    const float*    wts  = (const float*)d_in[2];
    const float*    gate = (const float*)d_in[3];
    const float*    up   = (const float*)d_in[4];
    const float*    down = (const float*)d_in[5];
    float* out = (float*)d_out;

    static int attr_done = 0;
    if (!attr_done) {
        cudaFuncSetAttribute(gemm1_kernel, cudaFuncAttributeMaxDynamicSharedMemorySize, G1_SMEM);
        cudaFuncSetAttribute(gemm2_kernel, cudaFuncAttributeMaxDynamicSharedMemorySize, G2_SMEM);
        attr_done = 1;
    }

    cudaMemsetAsync(out, 0, (size_t)out_size * sizeof(float));
    route_kernel<<<1, 256>>>(idx, wts);

    __nv_bfloat16 *gh, *gl, *uh, *ul, *dh, *dl, *xh, *xl;
    cudaGetSymbolAddress((void**)&gh, g_gh); cudaGetSymbolAddress((void**)&gl, g_gl);
    cudaGetSymbolAddress((void**)&uh, g_uh); cudaGetSymbolAddress((void**)&ul, g_ul);
    cudaGetSymbolAddress((void**)&dh, g_dh); cudaGetSymbolAddress((void**)&dl, g_dl);
    cudaGetSymbolAddress((void**)&xh, g_xh); cudaGetSymbolAddress((void**)&xl, g_xl);

    const size_t nw = NW;
    const size_t nx = (size_t)T_NUM * H_DIM;
    convertw_kernel<<<dim3((unsigned)(nw / 1024), 3), 256>>>(gate, gh, gl, up, uh, ul, down, dh, dl);
    convert_kernel<<<(unsigned)(nx / 1024), 256>>>(x, xh, xl, nx);

    gemm1_kernel<<<dim3(T_NUM / TM, I_DIM / TN, E_NUM), NTHREADS, G1_SMEM>>>();
    gemm2_kernel<<<dim3(T_NUM / TM, H_DIM / TN, E_NUM), NTHREADS, G2_SMEM>>>(out);
}